// round 6
// baseline (speedup 1.0000x reference)
#include <cuda_runtime.h>

#define IMG_W 1024
#define IMG_H 1024

// sigma=0.1 => exponent -50*d^2. Of the 5 taps/dim only offsets {0,1} carry
// representable weight (|d|>=1 raw weight <= e^-50, relative <= 5e-17 — below
// fp32 ulp), so the 5-tap normalizing sum collapses to 2 exps/dim exactly.
// Gate T=2e-3 on normalized weight; measured rel_err linear in T
// (2e-4 -> 3.0e-5, 1e-3 -> 1.5e-4, 2e-3 -> 3.0e-4), 3.3x under tolerance.
// Scalar 4B REDG per tap: R3/R5 established the binder is chip-wide atomic
// element throughput — instruction packing and small element cuts don't move it.
__device__ __forceinline__ void splat_one(float x, float y, float val,
                                          float* __restrict__ img)
{
    float xp = (x + 1.0f) * 512.0f;   // (x - X0)/DX, exact in fp32
    float yp = (y + 1.0f) * 512.0f;

    float fxb = floorf(xp), fyb = floorf(yp);
    int   xb  = (int)fxb,   yb  = (int)fyb;
    float fx  = xp - fxb,   fy  = yp - fyb;   // [0,1)

    float gx = 1.0f - fx, gy = 1.0f - fy;
    float ex0 = __expf(-50.0f * fx * fx);
    float ex1 = __expf(-50.0f * gx * gx);
    float ey0 = __expf(-50.0f * fy * fy);
    float ey1 = __expf(-50.0f * gy * gy);

    float sxy = (ex0 + ex1) * (ey0 + ey1);
    float vi  = __fdividef(val, sxy);

    float w00 = ex0 * ey0;
    float w10 = ex1 * ey0;
    float w01 = ex0 * ey1;
    float w11 = ex1 * ey1;

    const float T = 2e-3f;
    float t = T * sxy;                 // gate in un-normalized space

    bool x1ok = (xb + 1 < IMG_W);
    bool y1ok = (yb + 1 < IMG_H);

    float* p = img + yb * IMG_W + xb;
    if (w00 > t)                 atomicAdd(p,             w00 * vi);
    if (w10 > t && x1ok)         atomicAdd(p + 1,         w10 * vi);
    if (w01 > t && y1ok)         atomicAdd(p + IMG_W,     w01 * vi);
    if (w11 > t && x1ok && y1ok) atomicAdd(p + IMG_W + 1, w11 * vi);
}

// Persistent single-wave grid (148 SMs x 8 blocks of 256 thr), grid-stride
// over float4-packed points: no wave-2 straggler tail, uniform per-SM MLP.
__global__ __launch_bounds__(256)
void splat_kernel4(const float4* __restrict__ xs,
                   const float4* __restrict__ ys,
                   const float4* __restrict__ vs,
                   float* __restrict__ img, int n4)
{
    int stride = gridDim.x * blockDim.x;
    for (int i = blockIdx.x * blockDim.x + threadIdx.x; i < n4; i += stride) {
        float4 x4 = xs[i];
        float4 y4 = ys[i];
        float4 v4 = vs[i];
        splat_one(x4.x, y4.x, v4.x, img);
        splat_one(x4.y, y4.y, v4.y, img);
        splat_one(x4.z, y4.z, v4.z, img);
        splat_one(x4.w, y4.w, v4.w, img);
    }
}

// Scalar tail (n not divisible by 4) — never launched for n = 2,000,000.
__global__ void splat_kernel_tail(const float* __restrict__ xs,
                                  const float* __restrict__ ys,
                                  const float* __restrict__ vs,
                                  float* __restrict__ img, int start, int n)
{
    int i = start + blockIdx.x * blockDim.x + threadIdx.x;
    if (i < n) splat_one(xs[i], ys[i], vs[i], img);
}

extern "C" void kernel_launch(void* const* d_in, const int* in_sizes, int n_in,
                              void* d_out, int out_size) {
    const float* xs = (const float*)d_in[0];
    const float* ys = (const float*)d_in[1];
    const float* vs = (const float*)d_in[2];
    float* img = (float*)d_out;
    int n = in_sizes[0];

    // Zero the poisoned output via a memset graph node (cheaper than a kernel).
    cudaMemsetAsync(img, 0, (size_t)out_size * sizeof(float), 0);

    int n4 = n / 4;
    if (n4 > 0) {
        int blocks_needed = (n4 + 255) / 256;
        int grid = blocks_needed < 1184 ? blocks_needed : 1184;  // one full wave
        splat_kernel4<<<grid, 256>>>((const float4*)xs, (const float4*)ys,
                                     (const float4*)vs, img, n4);
    }
    int rem = n - n4 * 4;
    if (rem > 0)
        splat_kernel_tail<<<1, 32>>>(xs, ys, vs, img, n4 * 4, n);
}

// round 7
// speedup vs baseline: 1.0122x; 1.0122x over previous
#include <cuda_runtime.h>

#define IMG_W 1024
#define IMG_H 1024

// Zero the output image (harness poisons d_out with 0xAA). Fires the PDL
// trigger so the splat kernel's blocks can launch while this grid drains.
__global__ void zero_img_kernel(float4* __restrict__ img, int n4) {
    int i = blockIdx.x * blockDim.x + threadIdx.x;
    if (i < n4) img[i] = make_float4(0.f, 0.f, 0.f, 0.f);
#if __CUDA_ARCH__ >= 900
    cudaTriggerProgrammaticLaunchCompletion();
#endif
}

// sigma=0.1 => exponent -50*d^2. Of the 5 taps/dim only offsets {0,1} carry
// representable weight (|d|>=1 raw weight <= e^-50, relative <= 5e-17 — below
// fp32 ulp), so the 5-tap normalizing sum collapses to 2 exps/dim exactly.
// Gate T=2e-3 on normalized weight; measured rel_err linear in T
// (2e-4 -> 3.0e-5, 1e-3 -> 1.5e-4, 2e-3 -> 3.0e-4), 3.3x under tolerance.
// Scalar 4B REDG per tap: R3/R5 established the binder is chip-wide atomic
// element throughput; splat sits at that floor (~19us).
__device__ __forceinline__ void splat_one(float x, float y, float val,
                                          float* __restrict__ img)
{
    float xp = (x + 1.0f) * 512.0f;   // (x - X0)/DX, exact in fp32
    float yp = (y + 1.0f) * 512.0f;

    float fxb = floorf(xp), fyb = floorf(yp);
    int   xb  = (int)fxb,   yb  = (int)fyb;
    float fx  = xp - fxb,   fy  = yp - fyb;   // [0,1)

    float gx = 1.0f - fx, gy = 1.0f - fy;
    float ex0 = __expf(-50.0f * fx * fx);
    float ex1 = __expf(-50.0f * gx * gx);
    float ey0 = __expf(-50.0f * fy * fy);
    float ey1 = __expf(-50.0f * gy * gy);

    float sxy = (ex0 + ex1) * (ey0 + ey1);
    float vi  = __fdividef(val, sxy);

    float w00 = ex0 * ey0;
    float w10 = ex1 * ey0;
    float w01 = ex0 * ey1;
    float w11 = ex1 * ey1;

    const float T = 2e-3f;
    float t = T * sxy;                 // gate in un-normalized space

    bool x1ok = (xb + 1 < IMG_W);
    bool y1ok = (yb + 1 < IMG_H);

    float* p = img + yb * IMG_W + xb;
    if (w00 > t)                 atomicAdd(p,             w00 * vi);
    if (w10 > t && x1ok)         atomicAdd(p + 1,         w10 * vi);
    if (w01 > t && y1ok)         atomicAdd(p + IMG_W,     w01 * vi);
    if (w11 > t && x1ok && y1ok) atomicAdd(p + IMG_W + 1, w11 * vi);
}

// Single-wave persistent grid (forced 8 blocks/SM via launch bounds so all
// 1184 blocks are co-resident), grid-stride over float4-packed points.
// PDL: prefetch first inputs BEFORE the grid-dependency sync so the load
// latency overlaps the zero kernel's drain; atomics only after the sync.
__global__ void __launch_bounds__(256, 8)
splat_kernel4(const float4* __restrict__ xs,
              const float4* __restrict__ ys,
              const float4* __restrict__ vs,
              float* __restrict__ img, int n4)
{
    int stride = gridDim.x * blockDim.x;
    int i0 = blockIdx.x * blockDim.x + threadIdx.x;

    float4 x4, y4, v4;
    bool have = i0 < n4;
    if (have) { x4 = xs[i0]; y4 = ys[i0]; v4 = vs[i0]; }

#if __CUDA_ARCH__ >= 900
    cudaGridDependencySynchronize();   // wait for zero kernel's writes
#endif

    for (int i = i0; i < n4; i += stride) {
        if (i != i0) { x4 = xs[i]; y4 = ys[i]; v4 = vs[i]; }
        splat_one(x4.x, y4.x, v4.x, img);
        splat_one(x4.y, y4.y, v4.y, img);
        splat_one(x4.z, y4.z, v4.z, img);
        splat_one(x4.w, y4.w, v4.w, img);
    }
}

// Scalar tail (n not divisible by 4) — never launched for n = 2,000,000.
__global__ void splat_kernel_tail(const float* __restrict__ xs,
                                  const float* __restrict__ ys,
                                  const float* __restrict__ vs,
                                  float* __restrict__ img, int start, int n)
{
    int i = start + blockIdx.x * blockDim.x + threadIdx.x;
    if (i < n) splat_one(xs[i], ys[i], vs[i], img);
}

extern "C" void kernel_launch(void* const* d_in, const int* in_sizes, int n_in,
                              void* d_out, int out_size) {
    const float* xs = (const float*)d_in[0];
    const float* ys = (const float*)d_in[1];
    const float* vs = (const float*)d_in[2];
    float* img = (float*)d_out;
    int n = in_sizes[0];

    int nimg4 = out_size / 4;
    zero_img_kernel<<<(nimg4 + 255) / 256, 256>>>((float4*)img, nimg4);

    int n4 = n / 4;
    if (n4 > 0) {
        int blocks_needed = (n4 + 255) / 256;
        int grid = blocks_needed < 1184 ? blocks_needed : 1184;  // one wave

        cudaLaunchConfig_t cfg = {};
        cfg.gridDim  = dim3((unsigned)grid, 1, 1);
        cfg.blockDim = dim3(256, 1, 1);
        cfg.dynamicSmemBytes = 0;
        cfg.stream = 0;
        cudaLaunchAttribute attr;
        attr.id = cudaLaunchAttributeProgrammaticStreamSerialization;
        attr.val.programmaticStreamSerializationAllowed = 1;
        cfg.attrs = &attr;
        cfg.numAttrs = 1;
        cudaLaunchKernelEx(&cfg, splat_kernel4,
                           (const float4*)xs, (const float4*)ys,
                           (const float4*)vs, img, n4);
    }
    int rem = n - n4 * 4;
    if (rem > 0)
        splat_kernel_tail<<<1, 32>>>(xs, ys, vs, img, n4 * 4, n);
}